// round 2
// baseline (speedup 1.0000x reference)
#include <cuda_runtime.h>

// Problem constants
#define BB 4
#define NN 4096
#define DD 256

// Tiling
#define BM 64          // rows (i) per CTA
#define BN 64          // cols (j) per tile
#define NT 256         // threads per CTA

#define ATSTRIDE 68    // padded row stride (floats) for k-transposed tiles (16B-aligned, conflict-free)
#define ETSTRIDE 66    // padded row stride for E-transposed tile (float2-aligned)

// Shared memory layout (in floats)
#define OFF_AT   0
#define OFF_BT   (DD * ATSTRIDE)                    // 17408
#define OFF_BROW (2 * DD * ATSTRIDE)                // 34816
#define OFF_ET   (2 * DD * ATSTRIDE + BN * DD)      // 51200
#define OFF_ST   (OFF_ET + BN * ETSTRIDE)           // 55424
#define SMEM_FLOATS (OFF_ST + BN)                   // 55488
#define SMEM_BYTES (SMEM_FLOATS * 4)                // 221952 B

// out layout assumption: [delta_state (B*N) | delta_val (B*N*D)], fp32

__global__ __launch_bounds__(NT, 1)
void prop_kernel(const float* __restrict__ val,
                 const float* __restrict__ state,
                 float* __restrict__ out)
{
    extern __shared__ float smem[];
    float* sAT   = smem + OFF_AT;    // [k=256][i=64(+pad)]  val_i transposed
    float* sBT   = smem + OFF_BT;    // [k=256][j=64(+pad)]  val_j transposed
    float* sBrow = smem + OFF_BROW;  // [j=64][d=256]        val_j row-major
    float* sET   = smem + OFF_ET;    // [j=64][i=64(+pad)]   edges transposed
    float* sSt   = smem + OFF_ST;    // [j=64]               state_j
    float* sRed  = sET;              // alias: state-reduction scratch (used after loop)

    const int tid  = threadIdx.x;
    const int b    = blockIdx.y;
    const int i0   = blockIdx.x * BM;

    const float* valb = val + (size_t)b * NN * DD;

    // ---- load A tile (val_i) transposed into sAT (once) ----
    {
        const float4* vi4 = (const float4*)(valb + (size_t)i0 * DD);
        #pragma unroll
        for (int it = 0; it < (BM * DD / 4) / NT; ++it) {   // 16 iters
            int idx = tid + it * NT;
            int row = idx >> 6;     // 64 float4 per row
            int k4  = idx & 63;
            float4 v = vi4[row * 64 + k4];
            sAT[(4 * k4 + 0) * ATSTRIDE + row] = v.x;
            sAT[(4 * k4 + 1) * ATSTRIDE + row] = v.y;
            sAT[(4 * k4 + 2) * ATSTRIDE + row] = v.z;
            sAT[(4 * k4 + 3) * ATSTRIDE + row] = v.w;
        }
    }

    const int ty   = tid >> 4;   // 0..15 : i-fragment (4 rows)
    const int tx   = tid & 15;   // 0..15 : j-fragment (4 cols)
    const int g    = tid >> 5;   // warp id: i-group of 8 rows for GEMM2
    const int lane = tid & 31;   // d-chunk owner for GEMM2

    // GEMM2 accumulators: 8 rows x 8 floats (two float4 at d = 4*lane and d = 4*(lane+32))
    float4 Cv[8][2];
    #pragma unroll
    for (int r = 0; r < 8; ++r) {
        Cv[r][0] = make_float4(0.f, 0.f, 0.f, 0.f);
        Cv[r][1] = make_float4(0.f, 0.f, 0.f, 0.f);
    }
    // delta_state partials for rows 4*ty+r over this thread's j-slice
    float ds4[4] = {0.f, 0.f, 0.f, 0.f};

    const float scale = 0.0625f;   // 256^-0.5

    for (int j0 = 0; j0 < NN; j0 += BN) {
        __syncthreads();  // previous GEMM2 done reading sB*/sET

        // ---- load B tile (val_j): row-major AND k-transposed ----
        {
            const float4* vj4 = (const float4*)(valb + (size_t)j0 * DD);
            #pragma unroll
            for (int it = 0; it < (BN * DD / 4) / NT; ++it) {   // 16 iters
                int idx = tid + it * NT;
                int row = idx >> 6;
                int k4  = idx & 63;
                float4 v = vj4[row * 64 + k4];
                ((float4*)sBrow)[row * 64 + k4] = v;
                sBT[(4 * k4 + 0) * ATSTRIDE + row] = v.x;
                sBT[(4 * k4 + 1) * ATSTRIDE + row] = v.y;
                sBT[(4 * k4 + 2) * ATSTRIDE + row] = v.z;
                sBT[(4 * k4 + 3) * ATSTRIDE + row] = v.w;
            }
            if (tid < BN) sSt[tid] = state[(size_t)b * NN + j0 + tid];
        }
        __syncthreads();

        // ---- GEMM1: S[4x4] = Vi[4ty..][k] . Vj[4tx..][k] ----
        float ac[4][4];
        #pragma unroll
        for (int r = 0; r < 4; ++r)
            #pragma unroll
            for (int c = 0; c < 4; ++c) ac[r][c] = 0.f;

        #pragma unroll 4
        for (int k = 0; k < DD; ++k) {
            float4 av = *(const float4*)&sAT[k * ATSTRIDE + 4 * ty];
            float4 bv = *(const float4*)&sBT[k * ATSTRIDE + 4 * tx];
            float a[4] = {av.x, av.y, av.z, av.w};
            float c4[4] = {bv.x, bv.y, bv.z, bv.w};
            #pragma unroll
            for (int r = 0; r < 4; ++r)
                #pragma unroll
                for (int c = 0; c < 4; ++c)
                    ac[r][c] = fmaf(a[r], c4[c], ac[r][c]);
        }

        // ---- softsign + delta_state partial + write E transposed ----
        #pragma unroll
        for (int c = 0; c < 4; ++c) {
            float stj = sSt[4 * tx + c];
            #pragma unroll
            for (int r = 0; r < 4; ++r) {
                float s = ac[r][c] * scale;
                float e = s / (1.0f + fabsf(s));
                ds4[r] = fmaf(e, stj, ds4[r]);
                sET[(4 * tx + c) * ETSTRIDE + 4 * ty + r] = e;
            }
        }
        __syncthreads();

        // ---- GEMM2: Cv[i][d] += sum_j E[j][i] * Vj[j][d] ----
        #pragma unroll 2
        for (int j = 0; j < BN; ++j) {
            const float* erow = &sET[j * ETSTRIDE + 8 * g];
            float2 e01 = *(const float2*)(erow + 0);
            float2 e23 = *(const float2*)(erow + 2);
            float2 e45 = *(const float2*)(erow + 4);
            float2 e67 = *(const float2*)(erow + 6);
            float e[8] = {e01.x, e01.y, e23.x, e23.y, e45.x, e45.y, e67.x, e67.y};
            float4 b0 = *(const float4*)&sBrow[j * DD + 4 * lane];
            float4 b1 = *(const float4*)&sBrow[j * DD + 4 * (lane + 32)];
            #pragma unroll
            for (int r = 0; r < 8; ++r) {
                Cv[r][0].x = fmaf(e[r], b0.x, Cv[r][0].x);
                Cv[r][0].y = fmaf(e[r], b0.y, Cv[r][0].y);
                Cv[r][0].z = fmaf(e[r], b0.z, Cv[r][0].z);
                Cv[r][0].w = fmaf(e[r], b0.w, Cv[r][0].w);
                Cv[r][1].x = fmaf(e[r], b1.x, Cv[r][1].x);
                Cv[r][1].y = fmaf(e[r], b1.y, Cv[r][1].y);
                Cv[r][1].z = fmaf(e[r], b1.z, Cv[r][1].z);
                Cv[r][1].w = fmaf(e[r], b1.w, Cv[r][1].w);
            }
        }
    }

    // ---- store delta_val ----
    float* outv = out + (size_t)BB * NN;
    #pragma unroll
    for (int r = 0; r < 8; ++r) {
        size_t row = (size_t)b * NN + i0 + 8 * g + r;
        float4* p = (float4*)(outv + row * DD);
        p[lane]      = Cv[r][0];
        p[lane + 32] = Cv[r][1];
    }

    // ---- reduce and store delta_state ----
    __syncthreads();   // all GEMM2 reads of sET complete; safe to reuse as sRed
    #pragma unroll
    for (int r = 0; r < 4; ++r)
        sRed[(4 * ty + r) * 16 + tx] = ds4[r];
    __syncthreads();
    if (tid < BM) {
        float s = 0.f;
        #pragma unroll
        for (int t = 0; t < 16; ++t) s += sRed[tid * 16 + t];
        out[(size_t)b * NN + i0 + tid] = s;
    }
}

extern "C" void kernel_launch(void* const* d_in, const int* in_sizes, int n_in,
                              void* d_out, int out_size)
{
    const float* val   = (const float*)d_in[0];
    const float* state = (const float*)d_in[1];
    float* out = (float*)d_out;

    cudaFuncSetAttribute(prop_kernel,
                         cudaFuncAttributeMaxDynamicSharedMemorySize, SMEM_BYTES);

    dim3 grid(NN / BM, BB);
    prop_kernel<<<grid, NT, SMEM_BYTES>>>(val, state, out);
}

// round 5
// speedup vs baseline: 4.1742x; 4.1742x over previous
#include <cuda_runtime.h>

#define BB 4
#define NN 4096
#define DD 256
#define TM 128            // i-rows per CTA
#define TJ 32             // j-tile
#define NITER (NN / TJ)   // 128
#define NT 256            // 8 warps

#define VIS 260           // sVi row stride (floats): bank-perm 4g+tg
#define VJS 260           // sVj row stride
#define ES  44            // sE row stride: bank-perm 12g+tg

// smem map (floats)
#define OFF_VI 0
#define SZ_VI (TM * VIS)              // 33280
#define OFF_VJ (OFF_VI + SZ_VI)
#define SZ_VJ (TJ * VJS)              // 8320 (x2)
#define OFF_E  (OFF_VJ + 2 * SZ_VJ)
#define SZ_E   (TM * ES)              // 5632
#define OFF_ST (OFF_E + SZ_E)
#define SMEM_FLOATS (OFF_ST + 2 * TJ)
#define SMEM_BYTES  (SMEM_FLOATS * 4) // 222464 B

static __device__ __forceinline__ unsigned rna(float x) {
    unsigned r; asm("cvt.rna.tf32.f32 %0, %1;" : "=r"(r) : "f"(x)); return r;
}
static __device__ __forceinline__ float rnaf(float x) { return __uint_as_float(rna(x)); }

static __device__ __forceinline__ void mma8(float c[4],
        unsigned a0, unsigned a1, unsigned a2, unsigned a3,
        unsigned b0, unsigned b1) {
    asm volatile(
        "mma.sync.aligned.m16n8k8.row.col.f32.tf32.tf32.f32 "
        "{%0,%1,%2,%3},{%4,%5,%6,%7},{%8,%9},{%0,%1,%2,%3};"
        : "+f"(c[0]), "+f"(c[1]), "+f"(c[2]), "+f"(c[3])
        : "r"(a0), "r"(a1), "r"(a2), "r"(a3), "r"(b0), "r"(b1));
}

__global__ __launch_bounds__(NT)
void prop_mma(const float* __restrict__ val,
              const float* __restrict__ state,
              float* __restrict__ out)
{
    extern __shared__ float smem[];
    float* sVi = smem + OFF_VI;
    float* sVj = smem + OFF_VJ;
    float* sE  = smem + OFF_E;
    float* sSt = smem + OFF_ST;

    const int tid  = threadIdx.x;
    const int wid  = tid >> 5;
    const int lane = tid & 31;
    const int g    = lane >> 2;   // groupID (row within fragment)
    const int tg   = lane & 3;    // thread-in-group (col within fragment)
    const int iw   = wid * 16;    // warp's 16-row stripe

    const int b  = blockIdx.y;
    const int i0 = blockIdx.x * TM;
    const float* valb = val + (size_t)b * NN * DD;
    const float* stb  = state + (size_t)b * NN;

    // ---- preload Vi (tf32-rounded) ----
    {
        const float4* gv = (const float4*)(valb + (size_t)i0 * DD);
        #pragma unroll
        for (int it = 0; it < 32; ++it) {
            int idx = tid + it * NT;         // 0..8191
            int r = idx >> 6, d4 = (idx & 63) * 4;
            float4 v = gv[idx];
            float* p = sVi + r * VIS + d4;
            p[0] = rnaf(v.x); p[1] = rnaf(v.y); p[2] = rnaf(v.z); p[3] = rnaf(v.w);
        }
    }
    // ---- preload Vj tile 0 + state tile 0 ----
    {
        const float4* gv = (const float4*)valb;
        #pragma unroll
        for (int it = 0; it < 8; ++it) {
            int idx = tid + it * NT;         // 0..2047
            int r = idx >> 6, d4 = (idx & 63) * 4;
            float4 v = gv[idx];
            float* p = sVj + r * VJS + d4;
            p[0] = rnaf(v.x); p[1] = rnaf(v.y); p[2] = rnaf(v.z); p[3] = rnaf(v.w);
        }
        if (tid < TJ) sSt[tid] = stb[tid];
    }
    __syncthreads();

    float dac[32][4];
    #pragma unroll
    for (int n = 0; n < 32; ++n) { dac[n][0] = dac[n][1] = dac[n][2] = dac[n][3] = 0.f; }
    float ds0 = 0.f, ds1 = 0.f;
    float* sEw = sE + iw * ES;

    for (int t = 0; t < NITER; ++t) {
        const int buf = t & 1;
        const float* vjs = sVj + buf * SZ_VJ;

        // prefetch next Vj tile into registers (hidden under GEMM1)
        float4 pf[8];
        if (t + 1 < NITER) {
            const float4* gv = (const float4*)(valb + (size_t)(t + 1) * TJ * DD);
            #pragma unroll
            for (int it = 0; it < 8; ++it) pf[it] = gv[tid + it * NT];
        }

        // ---- GEMM1: S(16x32 stripe) = Vi . Vj^T over K=256 ----
        float cac[4][4];
        #pragma unroll
        for (int n = 0; n < 4; ++n) cac[n][0] = cac[n][1] = cac[n][2] = cac[n][3] = 0.f;

        const float* A0 = sVi + (iw + g) * VIS + tg;
        const float* A1 = sVi + (iw + g + 8) * VIS + tg;
        #pragma unroll 8
        for (int k0 = 0; k0 < DD; k0 += 8) {
            unsigned a0 = __float_as_uint(A0[k0]);
            unsigned a1 = __float_as_uint(A1[k0]);
            unsigned a2 = __float_as_uint(A0[k0 + 4]);
            unsigned a3 = __float_as_uint(A1[k0 + 4]);
            #pragma unroll
            for (int nt = 0; nt < 4; ++nt) {
                const float* Bp = vjs + (nt * 8 + g) * VJS + k0 + tg;
                mma8(cac[nt], a0, a1, a2, a3,
                     __float_as_uint(Bp[0]), __float_as_uint(Bp[4]));
            }
        }

        // ---- epilogue: softsign, delta_state partial, E -> smem (tf32) ----
        {
            const float* st = sSt + buf * TJ;
            #pragma unroll
            for (int nt = 0; nt < 4; ++nt) {
                int c0 = nt * 8 + 2 * tg;
                float2 sv = *(const float2*)(st + c0);
                float s00 = cac[nt][0] * 0.0625f, s01 = cac[nt][1] * 0.0625f;
                float s10 = cac[nt][2] * 0.0625f, s11 = cac[nt][3] * 0.0625f;
                float e00 = __fdividef(s00, 1.0f + fabsf(s00));
                float e01 = __fdividef(s01, 1.0f + fabsf(s01));
                float e10 = __fdividef(s10, 1.0f + fabsf(s10));
                float e11 = __fdividef(s11, 1.0f + fabsf(s11));
                ds0 = fmaf(e00, sv.x, fmaf(e01, sv.y, ds0));
                ds1 = fmaf(e10, sv.x, fmaf(e11, sv.y, ds1));
                *(float2*)(sEw + g * ES + c0)       = make_float2(rnaf(e00), rnaf(e01));
                *(float2*)(sEw + (g + 8) * ES + c0) = make_float2(rnaf(e10), rnaf(e11));
            }
        }
        __syncwarp();

        // ---- GEMM2: D(16x256 stripe) += E . Vj ----
        #pragma unroll
        for (int kk = 0; kk < 4; ++kk) {
            unsigned a0 = __float_as_uint(sEw[g * ES + kk * 8 + tg]);
            unsigned a1 = __float_as_uint(sEw[(g + 8) * ES + kk * 8 + tg]);
            unsigned a2 = __float_as_uint(sEw[g * ES + kk * 8 + tg + 4]);
            unsigned a3 = __float_as_uint(sEw[(g + 8) * ES + kk * 8 + tg + 4]);
            const float* Bb = vjs + (kk * 8 + tg) * VJS + g;
            #pragma unroll
            for (int nt = 0; nt < 32; ++nt) {
                mma8(dac[nt], a0, a1, a2, a3,
                     __float_as_uint(Bb[nt * 8]),
                     __float_as_uint(Bb[4 * VJS + nt * 8]));
            }
        }

        // ---- commit prefetch into alt buffer ----
        if (t + 1 < NITER) {
            float* dst = sVj + (buf ^ 1) * SZ_VJ;
            #pragma unroll
            for (int it = 0; it < 8; ++it) {
                int idx = tid + it * NT;
                int r = idx >> 6, d4 = (idx & 63) * 4;
                float4 v = pf[it];
                float* p = dst + r * VJS + d4;
                p[0] = rnaf(v.x); p[1] = rnaf(v.y); p[2] = rnaf(v.z); p[3] = rnaf(v.w);
            }
            if (tid < TJ) sSt[(buf ^ 1) * TJ + tid] = stb[(t + 1) * TJ + tid];
        }
        __syncthreads();
    }

    // ---- delta_state: quad reduce + store ----
    ds0 += __shfl_xor_sync(0xFFFFFFFFu, ds0, 1);
    ds0 += __shfl_xor_sync(0xFFFFFFFFu, ds0, 2);
    ds1 += __shfl_xor_sync(0xFFFFFFFFu, ds1, 1);
    ds1 += __shfl_xor_sync(0xFFFFFFFFu, ds1, 2);
    if (tg == 0) {
        out[(size_t)b * NN + i0 + iw + g]     = ds0;
        out[(size_t)b * NN + i0 + iw + g + 8] = ds1;
    }

    // ---- delta_val store ----
    float* ov = out + (size_t)BB * NN + ((size_t)b * NN + i0 + iw) * DD;
    #pragma unroll
    for (int nt = 0; nt < 32; ++nt) {
        int col = nt * 8 + 2 * tg;
        *(float2*)(ov + (size_t)g * DD + col)       = make_float2(dac[nt][0], dac[nt][1]);
        *(float2*)(ov + (size_t)(g + 8) * DD + col) = make_float2(dac[nt][2], dac[nt][3]);
    }
}

extern "C" void kernel_launch(void* const* d_in, const int* in_sizes, int n_in,
                              void* d_out, int out_size)
{
    const float* val   = (const float*)d_in[0];
    const float* state = (const float*)d_in[1];
    float* out = (float*)d_out;

    cudaFuncSetAttribute(prop_mma, cudaFuncAttributeMaxDynamicSharedMemorySize, SMEM_BYTES);

    dim3 grid(NN / TM, BB);
    prop_mma<<<grid, NT, SMEM_BYTES>>>(val, state, out);
}

// round 9
// speedup vs baseline: 5.6368x; 1.3504x over previous
#include <cuda_runtime.h>
#include <cstdint>

#define BB 4
#define NN 4096
#define DD 256
#define TM 128
#define TJ 64
#define NITER (NN / TJ)   // 64
#define NT 256            // 8 warps

#define VJS 260           // padded Vj row stride (floats)

// smem map (float offsets)
#define OFF_VI 0
#define SZ_VI (TM * DD)               // 32768 (XOR-swizzled, no pad)
#define OFF_VJ (OFF_VI + SZ_VI)       // 32768
#define SZ_VJ (TJ * VJS)              // 16640
#define OFF_E  (OFF_VJ + SZ_VJ)       // 49408 (XOR-swizzled [128][64])
#define SZ_E   (TM * TJ)              // 8192
#define OFF_ST (OFF_E + SZ_E)         // 57600
#define OFF_RED (OFF_ST + TJ)         // 57664
#define SMEM_FLOATS (OFF_RED + 2 * TM) // 57920
#define SMEM_BYTES  (SMEM_FLOATS * 4)  // 231680

// truncation-bias compensation: cp.async skips cvt.rna, mma truncates Vj (RZ).
// E[shrink] = 2^-11 relative; fold (1+2^-11) into scale and stored E.
#define SCALE1 0.06253051757813f   // 0.0625 * (1 + 2^-11)
#define ECOMP  1.00048828125f      // 1 + 2^-11

static __device__ __forceinline__ unsigned rna(float x) {
    unsigned r; asm("cvt.rna.tf32.f32 %0, %1;" : "=r"(r) : "f"(x)); return r;
}
static __device__ __forceinline__ float rnaf(float x) { return __uint_as_float(rna(x)); }

static __device__ __forceinline__ void mma8(float c[4],
        unsigned a0, unsigned a1, unsigned a2, unsigned a3,
        unsigned b0, unsigned b1) {
    asm volatile(
        "mma.sync.aligned.m16n8k8.row.col.f32.tf32.tf32.f32 "
        "{%0,%1,%2,%3},{%4,%5,%6,%7},{%8,%9},{%0,%1,%2,%3};"
        : "+f"(c[0]), "+f"(c[1]), "+f"(c[2]), "+f"(c[3])
        : "r"(a0), "r"(a1), "r"(a2), "r"(a3), "r"(b0), "r"(b1));
}

static __device__ __forceinline__ unsigned smem_u32(const void* p) {
    unsigned a;
    asm("{ .reg .u64 t; cvta.to.shared.u64 t, %1; cvt.u32.u64 %0, t; }" : "=r"(a) : "l"(p));
    return a;
}

#define CP16(dst, src) asm volatile("cp.async.cg.shared.global [%0], [%1], 16;" \
    :: "r"(dst), "l"(src) : "memory")
#define CP4(dst, src)  asm volatile("cp.async.ca.shared.global [%0], [%1], 4;" \
    :: "r"(dst), "l"(src) : "memory")
#define CP_COMMIT() asm volatile("cp.async.commit_group;" ::: "memory")
#define CP_WAIT0()  asm volatile("cp.async.wait_group 0;" ::: "memory")

__global__ __launch_bounds__(NT)
void prop_mma2(const float* __restrict__ val,
               const float* __restrict__ state,
               float* __restrict__ out)
{
    extern __shared__ float smem[];
    float* sVi = smem + OFF_VI;
    float* sVj = smem + OFF_VJ;
    float* sE  = smem + OFF_E;
    float* sSt = smem + OFF_ST;
    float* sRed = smem + OFF_RED;

    const int tid  = threadIdx.x;
    const int wid  = tid >> 5;
    const int lane = tid & 31;
    const int g    = lane >> 2;   // fragment row
    const int tg   = lane & 3;    // fragment col
    const unsigned xg = 4u * (unsigned)g;   // XOR swizzle key (r&7 == g for all frag rows)

    // GEMM1 warp grid: 4(i) x 2(j), tile 32x32
    const int wi = wid >> 1, wj = wid & 1;
    // GEMM2 warp grid: 2(i) x 4(d), tile 64x64
    const int rb = wid >> 2, cb = wid & 3;

    const int b  = blockIdx.y;
    const int i0 = blockIdx.x * TM;
    const float* valb = val + (size_t)b * NN * DD;
    const float* stb  = state + (size_t)b * NN;

    const unsigned sbVj = smem_u32(sVj);
    const unsigned sbSt = smem_u32(sSt);

    // ---- preload Vi (rna-rounded, XOR swizzle: (r,k) -> r*256 + (k ^ 4*(r&7))) ----
    {
        const float4* gv = (const float4*)(valb + (size_t)i0 * DD);
        #pragma unroll
        for (int it = 0; it < 32; ++it) {
            int idx = tid + it * NT;
            int r = idx >> 6, c4 = (idx & 63) * 4;
            float4 v = gv[idx];
            unsigned cc = (unsigned)c4 ^ (4u * (r & 7));
            *(float4*)(sVi + r * DD + cc) =
                make_float4(rnaf(v.x), rnaf(v.y), rnaf(v.z), rnaf(v.w));
        }
    }
    // ---- cp.async fill Vj tile 0 + state tile 0 ----
    {
        #pragma unroll
        for (int it = 0; it < 16; ++it) {
            int idx = tid + it * NT;
            int r = idx >> 6, c = idx & 63;
            CP16(sbVj + (unsigned)(r * VJS + c * 4) * 4, valb + r * DD + c * 4);
        }
        if (tid < TJ) CP4(sbSt + tid * 4, stb + tid);
        CP_COMMIT(); CP_WAIT0();
    }
    __syncthreads();

    float dac[4][8][4];
    #pragma unroll
    for (int mf = 0; mf < 4; ++mf)
        #pragma unroll
        for (int nf = 0; nf < 8; ++nf)
            dac[mf][nf][0] = dac[mf][nf][1] = dac[mf][nf][2] = dac[mf][nf][3] = 0.f;
    float ds[4] = {0.f, 0.f, 0.f, 0.f};

    const float* A0 = sVi + (wi * 32 + g) * DD;          // GEMM1 A base
    const float* B1 = sVj + (wj * 32 + g) * VJS + tg;    // GEMM1 B base
    const float* E0 = sE  + (rb * 64 + g) * TJ;          // GEMM2 A base
    const float* B2 = sVj + tg * VJS + cb * 64 + g;      // GEMM2 B base

    for (int t = 0; t < NITER; ++t) {
        // ---- GEMM1: S(32x32) = Vi . Vj^T over K=256 ----
        float cac[2][4][4];
        #pragma unroll
        for (int mf = 0; mf < 2; ++mf)
            #pragma unroll
            for (int nf = 0; nf < 4; ++nf)
                cac[mf][nf][0] = cac[mf][nf][1] = cac[mf][nf][2] = cac[mf][nf][3] = 0.f;

        #pragma unroll 8
        for (int k0 = 0; k0 < DD; k0 += 8) {
            unsigned ka = ((unsigned)(k0 + tg)) ^ xg;
            unsigned kb = ((unsigned)(k0 + 4 + tg)) ^ xg;
            unsigned a[2][4];
            #pragma unroll
            for (int mf = 0; mf < 2; ++mf) {
                const float* Ap = A0 + mf * 16 * DD;
                a[mf][0] = __float_as_uint(Ap[ka]);
                a[mf][1] = __float_as_uint(Ap[8 * DD + ka]);
                a[mf][2] = __float_as_uint(Ap[kb]);
                a[mf][3] = __float_as_uint(Ap[8 * DD + kb]);
            }
            #pragma unroll
            for (int nf = 0; nf < 4; ++nf) {
                unsigned b0 = __float_as_uint(B1[nf * 8 * VJS + k0]);
                unsigned b1 = __float_as_uint(B1[nf * 8 * VJS + k0 + 4]);
                mma8(cac[0][nf], a[0][0], a[0][1], a[0][2], a[0][3], b0, b1);
                mma8(cac[1][nf], a[1][0], a[1][1], a[1][2], a[1][3], b0, b1);
            }
        }

        // ---- epilogue: softsign, ds partials, E -> smem (tf32, compensated) ----
        #pragma unroll
        for (int mf = 0; mf < 2; ++mf) {
            #pragma unroll
            for (int nf = 0; nf < 4; ++nf) {
                float2 sv = *(const float2*)(sSt + wj * 32 + nf * 8 + 2 * tg);
                float s00 = cac[mf][nf][0] * SCALE1, s01 = cac[mf][nf][1] * SCALE1;
                float s10 = cac[mf][nf][2] * SCALE1, s11 = cac[mf][nf][3] * SCALE1;
                float e00 = __fdividef(s00, 1.0f + fabsf(s00));
                float e01 = __fdividef(s01, 1.0f + fabsf(s01));
                float e10 = __fdividef(s10, 1.0f + fabsf(s10));
                float e11 = __fdividef(s11, 1.0f + fabsf(s11));
                ds[2 * mf]     = fmaf(e00, sv.x, fmaf(e01, sv.y, ds[2 * mf]));
                ds[2 * mf + 1] = fmaf(e10, sv.x, fmaf(e11, sv.y, ds[2 * mf + 1]));
                unsigned jc = ((unsigned)(wj * 32 + nf * 8 + 2 * tg)) ^ xg;
                int r0 = wi * 32 + mf * 16 + g;
                *(float2*)(sE + r0 * TJ + jc) =
                    make_float2(rnaf(e00 * ECOMP), rnaf(e01 * ECOMP));
                *(float2*)(sE + (r0 + 8) * TJ + jc) =
                    make_float2(rnaf(e10 * ECOMP), rnaf(e11 * ECOMP));
            }
        }
        __syncthreads();   // A: E complete

        // ---- GEMM2: D(64x64) += E . Vj over K=64 ----
        #pragma unroll
        for (int kk = 0; kk < 8; ++kk) {
            unsigned ka = ((unsigned)(kk * 8 + tg)) ^ xg;
            unsigned kb = ((unsigned)(kk * 8 + 4 + tg)) ^ xg;
            unsigned a[4][4];
            #pragma unroll
            for (int mf = 0; mf < 4; ++mf) {
                const float* Ep = E0 + mf * 16 * TJ;
                a[mf][0] = __float_as_uint(Ep[ka]);
                a[mf][1] = __float_as_uint(Ep[8 * TJ + ka]);
                a[mf][2] = __float_as_uint(Ep[kb]);
                a[mf][3] = __float_as_uint(Ep[8 * TJ + kb]);
            }
            const float* Bk = B2 + kk * 8 * VJS;
            #pragma unroll
            for (int nf = 0; nf < 8; ++nf) {
                unsigned b0 = __float_as_uint(Bk[nf * 8]);
                unsigned b1 = __float_as_uint(Bk[4 * VJS + nf * 8]);
                #pragma unroll
                for (int mf = 0; mf < 4; ++mf)
                    mma8(dac[mf][nf], a[mf][0], a[mf][1], a[mf][2], a[mf][3], b0, b1);
            }
        }
        __syncthreads();   // B: sVj / sE / sSt free

        // ---- cp.async fill Vj(t+1) + state(t+1) ----
        if (t + 1 < NITER) {
            const float* gsrc = valb + (size_t)(t + 1) * TJ * DD;
            #pragma unroll
            for (int it = 0; it < 16; ++it) {
                int idx = tid + it * NT;
                int r = idx >> 6, c = idx & 63;
                CP16(sbVj + (unsigned)(r * VJS + c * 4) * 4, gsrc + r * DD + c * 4);
            }
            if (tid < TJ) CP4(sbSt + tid * 4, stb + (t + 1) * TJ + tid);
            CP_COMMIT(); CP_WAIT0();
            __syncthreads();   // C: new tile visible
        }
    }

    // ---- delta_state: quad reduce, cross-warp (wj) reduce via smem ----
    #pragma unroll
    for (int q = 0; q < 4; ++q) {
        ds[q] += __shfl_xor_sync(0xFFFFFFFFu, ds[q], 1);
        ds[q] += __shfl_xor_sync(0xFFFFFFFFu, ds[q], 2);
    }
    if (tg == 0) {
        #pragma unroll
        for (int q = 0; q < 4; ++q) {
            int row = wi * 32 + (q >> 1) * 16 + (q & 1) * 8 + g;
            sRed[wj * TM + row] = ds[q];
        }
    }
    __syncthreads();
    if (tid < TM)
        out[(size_t)b * NN + i0 + tid] = sRed[tid] + sRed[TM + tid];

    // ---- delta_val store ----
    float* ov = out + (size_t)BB * NN
              + ((size_t)b * NN + i0 + rb * 64) * DD + cb * 64;
    #pragma unroll
    for (int mf = 0; mf < 4; ++mf) {
        #pragma unroll
        for (int nf = 0; nf < 8; ++nf) {
            int col = nf * 8 + 2 * tg;
            size_t r0 = (size_t)(mf * 16 + g) * DD;
            *(float2*)(ov + r0 + col)            = make_float2(dac[mf][nf][0], dac[mf][nf][1]);
            *(float2*)(ov + r0 + 8 * DD + col)   = make_float2(dac[mf][nf][2], dac[mf][nf][3]);
        }
    }
}

extern "C" void kernel_launch(void* const* d_in, const int* in_sizes, int n_in,
                              void* d_out, int out_size)
{
    const float* val   = (const float*)d_in[0];
    const float* state = (const float*)d_in[1];
    float* out = (float*)d_out;

    cudaFuncSetAttribute(prop_mma2, cudaFuncAttributeMaxDynamicSharedMemorySize, SMEM_BYTES);

    dim3 grid(NN / TM, BB);
    prop_mma2<<<grid, NT, SMEM_BYTES>>>(val, state, out);
}

// round 11
// speedup vs baseline: 5.6380x; 1.0002x over previous
#include <cuda_runtime.h>
#include <cstdint>

#define BB 4
#define NN 4096
#define DD 256
#define TM 128
#define TJ 64
#define NITER (NN / TJ)   // 64
#define NT 256            // 8 warps

#define VJS 260           // padded Vj row stride (floats)

// smem map (float offsets)
#define OFF_VI 0
#define SZ_VI (TM * DD)               // 32768 (XOR-swizzled, no pad)
#define OFF_VJ (OFF_VI + SZ_VI)       // 32768
#define SZ_VJ (TJ * VJS)              // 16640
#define OFF_E  (OFF_VJ + SZ_VJ)       // 49408 (XOR-swizzled [128][64])
#define SZ_E   (TM * TJ)              // 8192
#define OFF_ST (OFF_E + SZ_E)         // 57600
#define OFF_RED (OFF_ST + TJ)         // 57664
#define SMEM_FLOATS (OFF_RED + 2 * TM) // 57920
#define SMEM_BYTES  (SMEM_FLOATS * 4)  // 231680

// truncation-bias compensation: cp.async skips cvt.rna, mma truncates Vj (RZ).
// E[shrink] = 2^-11 relative; fold (1+2^-11) into scale and stored E.
#define SCALE1 0.06253051757813f   // 0.0625 * (1 + 2^-11)
#define ECOMP  1.00048828125f      // 1 + 2^-11

static __device__ __forceinline__ unsigned rna(float x) {
    unsigned r; asm("cvt.rna.tf32.f32 %0, %1;" : "=r"(r) : "f"(x)); return r;
}
static __device__ __forceinline__ float rnaf(float x) { return __uint_as_float(rna(x)); }

static __device__ __forceinline__ void mma8(float c[4],
        unsigned a0, unsigned a1, unsigned a2, unsigned a3,
        unsigned b0, unsigned b1) {
    asm volatile(
        "mma.sync.aligned.m16n8k8.row.col.f32.tf32.tf32.f32 "
        "{%0,%1,%2,%3},{%4,%5,%6,%7},{%8,%9},{%0,%1,%2,%3};"
        : "+f"(c[0]), "+f"(c[1]), "+f"(c[2]), "+f"(c[3])
        : "r"(a0), "r"(a1), "r"(a2), "r"(a3), "r"(b0), "r"(b1));
}

static __device__ __forceinline__ unsigned smem_u32(const void* p) {
    unsigned a;
    asm("{ .reg .u64 t; cvta.to.shared.u64 t, %1; cvt.u32.u64 %0, t; }" : "=r"(a) : "l"(p));
    return a;
}

#define CP16(dst, src) asm volatile("cp.async.cg.shared.global [%0], [%1], 16;" \
    :: "r"(dst), "l"(src) : "memory")
#define CP4(dst, src)  asm volatile("cp.async.ca.shared.global [%0], [%1], 4;" \
    :: "r"(dst), "l"(src) : "memory")
#define CP_COMMIT() asm volatile("cp.async.commit_group;" ::: "memory")
#define CP_WAIT0()  asm volatile("cp.async.wait_group 0;" ::: "memory")

__global__ __launch_bounds__(NT)
void prop_mma2(const float* __restrict__ val,
               const float* __restrict__ state,
               float* __restrict__ out)
{
    extern __shared__ float smem[];
    float* sVi = smem + OFF_VI;
    float* sVj = smem + OFF_VJ;
    float* sE  = smem + OFF_E;
    float* sSt = smem + OFF_ST;
    float* sRed = smem + OFF_RED;

    const int tid  = threadIdx.x;
    const int wid  = tid >> 5;
    const int lane = tid & 31;
    const int g    = lane >> 2;   // fragment row
    const int tg   = lane & 3;    // fragment col
    const unsigned xg = 4u * (unsigned)g;   // XOR swizzle key (r&7 == g for all frag rows)

    // GEMM1 warp grid: 4(i) x 2(j), tile 32x32
    const int wi = wid >> 1, wj = wid & 1;
    // GEMM2 warp grid: 2(i) x 4(d), tile 64x64
    const int rb = wid >> 2, cb = wid & 3;

    const int b  = blockIdx.y;
    const int i0 = blockIdx.x * TM;
    const float* valb = val + (size_t)b * NN * DD;
    const float* stb  = state + (size_t)b * NN;

    const unsigned sbVj = smem_u32(sVj);
    const unsigned sbSt = smem_u32(sSt);

    // ---- preload Vi (rna-rounded, XOR swizzle: (r,k) -> r*256 + (k ^ 4*(r&7))) ----
    {
        const float4* gv = (const float4*)(valb + (size_t)i0 * DD);
        #pragma unroll
        for (int it = 0; it < 32; ++it) {
            int idx = tid + it * NT;
            int r = idx >> 6, c4 = (idx & 63) * 4;
            float4 v = gv[idx];
            unsigned cc = (unsigned)c4 ^ (4u * (r & 7));
            *(float4*)(sVi + r * DD + cc) =
                make_float4(rnaf(v.x), rnaf(v.y), rnaf(v.z), rnaf(v.w));
        }
    }
    // ---- cp.async fill Vj tile 0 + state tile 0 ----
    {
        #pragma unroll
        for (int it = 0; it < 16; ++it) {
            int idx = tid + it * NT;
            int r = idx >> 6, c = idx & 63;
            CP16(sbVj + (unsigned)(r * VJS + c * 4) * 4, valb + r * DD + c * 4);
        }
        if (tid < TJ) CP4(sbSt + tid * 4, stb + tid);
        CP_COMMIT(); CP_WAIT0();
    }
    __syncthreads();

    float dac[4][8][4];
    #pragma unroll
    for (int mf = 0; mf < 4; ++mf)
        #pragma unroll
        for (int nf = 0; nf < 8; ++nf)
            dac[mf][nf][0] = dac[mf][nf][1] = dac[mf][nf][2] = dac[mf][nf][3] = 0.f;
    float ds[4] = {0.f, 0.f, 0.f, 0.f};

    const float* A0 = sVi + (wi * 32 + g) * DD;          // GEMM1 A base
    const float* B1 = sVj + (wj * 32 + g) * VJS + tg;    // GEMM1 B base
    const float* E0 = sE  + (rb * 64 + g) * TJ;          // GEMM2 A base
    const float* B2 = sVj + tg * VJS + cb * 64 + g;      // GEMM2 B base

    for (int t = 0; t < NITER; ++t) {
        // ---- GEMM1: S(32x32) = Vi . Vj^T over K=256 ----
        float cac[2][4][4];
        #pragma unroll
        for (int mf = 0; mf < 2; ++mf)
            #pragma unroll
            for (int nf = 0; nf < 4; ++nf)
                cac[mf][nf][0] = cac[mf][nf][1] = cac[mf][nf][2] = cac[mf][nf][3] = 0.f;

        #pragma unroll 8
        for (int k0 = 0; k0 < DD; k0 += 8) {
            unsigned ka = ((unsigned)(k0 + tg)) ^ xg;
            unsigned kb = ((unsigned)(k0 + 4 + tg)) ^ xg;
            unsigned a[2][4];
            #pragma unroll
            for (int mf = 0; mf < 2; ++mf) {
                const float* Ap = A0 + mf * 16 * DD;
                a[mf][0] = __float_as_uint(Ap[ka]);
                a[mf][1] = __float_as_uint(Ap[8 * DD + ka]);
                a[mf][2] = __float_as_uint(Ap[kb]);
                a[mf][3] = __float_as_uint(Ap[8 * DD + kb]);
            }
            #pragma unroll
            for (int nf = 0; nf < 4; ++nf) {
                unsigned b0 = __float_as_uint(B1[nf * 8 * VJS + k0]);
                unsigned b1 = __float_as_uint(B1[nf * 8 * VJS + k0 + 4]);
                mma8(cac[0][nf], a[0][0], a[0][1], a[0][2], a[0][3], b0, b1);
                mma8(cac[1][nf], a[1][0], a[1][1], a[1][2], a[1][3], b0, b1);
            }
        }

        // ---- epilogue: softsign, ds partials, E -> smem (tf32, compensated) ----
        #pragma unroll
        for (int mf = 0; mf < 2; ++mf) {
            #pragma unroll
            for (int nf = 0; nf < 4; ++nf) {
                float2 sv = *(const float2*)(sSt + wj * 32 + nf * 8 + 2 * tg);
                float s00 = cac[mf][nf][0] * SCALE1, s01 = cac[mf][nf][1] * SCALE1;
                float s10 = cac[mf][nf][2] * SCALE1, s11 = cac[mf][nf][3] * SCALE1;
                float e00 = __fdividef(s00, 1.0f + fabsf(s00));
                float e01 = __fdividef(s01, 1.0f + fabsf(s01));
                float e10 = __fdividef(s10, 1.0f + fabsf(s10));
                float e11 = __fdividef(s11, 1.0f + fabsf(s11));
                ds[2 * mf]     = fmaf(e00, sv.x, fmaf(e01, sv.y, ds[2 * mf]));
                ds[2 * mf + 1] = fmaf(e10, sv.x, fmaf(e11, sv.y, ds[2 * mf + 1]));
                unsigned jc = ((unsigned)(wj * 32 + nf * 8 + 2 * tg)) ^ xg;
                int r0 = wi * 32 + mf * 16 + g;
                *(float2*)(sE + r0 * TJ + jc) =
                    make_float2(rnaf(e00 * ECOMP), rnaf(e01 * ECOMP));
                *(float2*)(sE + (r0 + 8) * TJ + jc) =
                    make_float2(rnaf(e10 * ECOMP), rnaf(e11 * ECOMP));
            }
        }
        __syncthreads();   // A: E complete

        // ---- GEMM2: D(64x64) += E . Vj over K=64 ----
        #pragma unroll
        for (int kk = 0; kk < 8; ++kk) {
            unsigned ka = ((unsigned)(kk * 8 + tg)) ^ xg;
            unsigned kb = ((unsigned)(kk * 8 + 4 + tg)) ^ xg;
            unsigned a[4][4];
            #pragma unroll
            for (int mf = 0; mf < 4; ++mf) {
                const float* Ep = E0 + mf * 16 * TJ;
                a[mf][0] = __float_as_uint(Ep[ka]);
                a[mf][1] = __float_as_uint(Ep[8 * TJ + ka]);
                a[mf][2] = __float_as_uint(Ep[kb]);
                a[mf][3] = __float_as_uint(Ep[8 * TJ + kb]);
            }
            const float* Bk = B2 + kk * 8 * VJS;
            #pragma unroll
            for (int nf = 0; nf < 8; ++nf) {
                unsigned b0 = __float_as_uint(Bk[nf * 8]);
                unsigned b1 = __float_as_uint(Bk[4 * VJS + nf * 8]);
                #pragma unroll
                for (int mf = 0; mf < 4; ++mf)
                    mma8(dac[mf][nf], a[mf][0], a[mf][1], a[mf][2], a[mf][3], b0, b1);
            }
        }
        __syncthreads();   // B: sVj / sE / sSt free

        // ---- cp.async fill Vj(t+1) + state(t+1) ----
        if (t + 1 < NITER) {
            const float* gsrc = valb + (size_t)(t + 1) * TJ * DD;
            #pragma unroll
            for (int it = 0; it < 16; ++it) {
                int idx = tid + it * NT;
                int r = idx >> 6, c = idx & 63;
                CP16(sbVj + (unsigned)(r * VJS + c * 4) * 4, gsrc + r * DD + c * 4);
            }
            if (tid < TJ) CP4(sbSt + tid * 4, stb + (t + 1) * TJ + tid);
            CP_COMMIT(); CP_WAIT0();
            __syncthreads();   // C: new tile visible
        }
    }

    // ---- delta_state: quad reduce, cross-warp (wj) reduce via smem ----
    #pragma unroll
    for (int q = 0; q < 4; ++q) {
        ds[q] += __shfl_xor_sync(0xFFFFFFFFu, ds[q], 1);
        ds[q] += __shfl_xor_sync(0xFFFFFFFFu, ds[q], 2);
    }
    if (tg == 0) {
        #pragma unroll
        for (int q = 0; q < 4; ++q) {
            int row = wi * 32 + (q >> 1) * 16 + (q & 1) * 8 + g;
            sRed[wj * TM + row] = ds[q];
        }
    }
    __syncthreads();
    if (tid < TM)
        out[(size_t)b * NN + i0 + tid] = sRed[tid] + sRed[TM + tid];

    // ---- delta_val store ----
    float* ov = out + (size_t)BB * NN
              + ((size_t)b * NN + i0 + rb * 64) * DD + cb * 64;
    #pragma unroll
    for (int mf = 0; mf < 4; ++mf) {
        #pragma unroll
        for (int nf = 0; nf < 8; ++nf) {
            int col = nf * 8 + 2 * tg;
            size_t r0 = (size_t)(mf * 16 + g) * DD;
            *(float2*)(ov + r0 + col)            = make_float2(dac[mf][nf][0], dac[mf][nf][1]);
            *(float2*)(ov + r0 + 8 * DD + col)   = make_float2(dac[mf][nf][2], dac[mf][nf][3]);
        }
    }
}

extern "C" void kernel_launch(void* const* d_in, const int* in_sizes, int n_in,
                              void* d_out, int out_size)
{
    const float* val   = (const float*)d_in[0];
    const float* state = (const float*)d_in[1];
    float* out = (float*)d_out;

    cudaFuncSetAttribute(prop_mma2, cudaFuncAttributeMaxDynamicSharedMemorySize, SMEM_BYTES);

    dim3 grid(NN / TM, BB);
    prop_mma2<<<grid, NT, SMEM_BYTES>>>(val, state, out);
}

// round 16
// speedup vs baseline: 5.6384x; 1.0001x over previous
#include <cuda_runtime.h>
#include <cstdint>

#define BB 4
#define NN 4096
#define DD 256
#define TM 128
#define TJ 64
#define NITER (NN / TJ)   // 64
#define NT 256            // 8 warps

#define VJS 260           // padded Vj row stride (floats)

// smem map (float offsets)
#define OFF_VI 0
#define SZ_VI (TM * DD)               // 32768 (XOR-swizzled, no pad)
#define OFF_VJ (OFF_VI + SZ_VI)       // 32768
#define SZ_VJ (TJ * VJS)              // 16640
#define OFF_E  (OFF_VJ + SZ_VJ)       // 49408 (XOR-swizzled [128][64])
#define SZ_E   (TM * TJ)              // 8192
#define OFF_ST (OFF_E + SZ_E)         // 57600
#define OFF_RED (OFF_ST + TJ)         // 57664
#define SMEM_FLOATS (OFF_RED + 2 * TM) // 57920
#define SMEM_BYTES  (SMEM_FLOATS * 4)  // 231680

// truncation-bias compensation: cp.async skips cvt.rna, mma truncates Vj (RZ).
// E[shrink] = 2^-11 relative; fold (1+2^-11) into scale and stored E.
#define SCALE1 0.06253051757813f   // 0.0625 * (1 + 2^-11)
#define ECOMP  1.00048828125f      // 1 + 2^-11

static __device__ __forceinline__ unsigned rna(float x) {
    unsigned r; asm("cvt.rna.tf32.f32 %0, %1;" : "=r"(r) : "f"(x)); return r;
}
static __device__ __forceinline__ float rnaf(float x) { return __uint_as_float(rna(x)); }

static __device__ __forceinline__ void mma8(float c[4],
        unsigned a0, unsigned a1, unsigned a2, unsigned a3,
        unsigned b0, unsigned b1) {
    asm volatile(
        "mma.sync.aligned.m16n8k8.row.col.f32.tf32.tf32.f32 "
        "{%0,%1,%2,%3},{%4,%5,%6,%7},{%8,%9},{%0,%1,%2,%3};"
        : "+f"(c[0]), "+f"(c[1]), "+f"(c[2]), "+f"(c[3])
        : "r"(a0), "r"(a1), "r"(a2), "r"(a3), "r"(b0), "r"(b1));
}

static __device__ __forceinline__ unsigned smem_u32(const void* p) {
    unsigned a;
    asm("{ .reg .u64 t; cvta.to.shared.u64 t, %1; cvt.u32.u64 %0, t; }" : "=r"(a) : "l"(p));
    return a;
}

#define CP16(dst, src) asm volatile("cp.async.cg.shared.global [%0], [%1], 16;" \
    :: "r"(dst), "l"(src) : "memory")
#define CP4(dst, src)  asm volatile("cp.async.ca.shared.global [%0], [%1], 4;" \
    :: "r"(dst), "l"(src) : "memory")
#define CP_COMMIT() asm volatile("cp.async.commit_group;" ::: "memory")
#define CP_WAIT0()  asm volatile("cp.async.wait_group 0;" ::: "memory")

__global__ __launch_bounds__(NT)
void prop_mma2(const float* __restrict__ val,
               const float* __restrict__ state,
               float* __restrict__ out)
{
    extern __shared__ float smem[];
    float* sVi = smem + OFF_VI;
    float* sVj = smem + OFF_VJ;
    float* sE  = smem + OFF_E;
    float* sSt = smem + OFF_ST;
    float* sRed = smem + OFF_RED;

    const int tid  = threadIdx.x;
    const int wid  = tid >> 5;
    const int lane = tid & 31;
    const int g    = lane >> 2;   // fragment row
    const int tg   = lane & 3;    // fragment col
    const unsigned xg = 4u * (unsigned)g;   // XOR swizzle key (r&7 == g for all frag rows)

    // GEMM1 warp grid: 4(i) x 2(j), tile 32x32
    const int wi = wid >> 1, wj = wid & 1;
    // GEMM2 warp grid: 2(i) x 4(d), tile 64x64
    const int rb = wid >> 2, cb = wid & 3;

    const int b  = blockIdx.y;
    const int i0 = blockIdx.x * TM;
    const float* valb = val + (size_t)b * NN * DD;
    const float* stb  = state + (size_t)b * NN;

    const unsigned sbVj = smem_u32(sVj);
    const unsigned sbSt = smem_u32(sSt);

    // ---- preload Vi (rna-rounded, XOR swizzle: (r,k) -> r*256 + (k ^ 4*(r&7))) ----
    {
        const float4* gv = (const float4*)(valb + (size_t)i0 * DD);
        #pragma unroll
        for (int it = 0; it < 32; ++it) {
            int idx = tid + it * NT;
            int r = idx >> 6, c4 = (idx & 63) * 4;
            float4 v = gv[idx];
            unsigned cc = (unsigned)c4 ^ (4u * (r & 7));
            *(float4*)(sVi + r * DD + cc) =
                make_float4(rnaf(v.x), rnaf(v.y), rnaf(v.z), rnaf(v.w));
        }
    }
    // ---- cp.async fill Vj tile 0 + state tile 0 ----
    {
        #pragma unroll
        for (int it = 0; it < 16; ++it) {
            int idx = tid + it * NT;
            int r = idx >> 6, c = idx & 63;
            CP16(sbVj + (unsigned)(r * VJS + c * 4) * 4, valb + r * DD + c * 4);
        }
        if (tid < TJ) CP4(sbSt + tid * 4, stb + tid);
        CP_COMMIT(); CP_WAIT0();
    }
    __syncthreads();

    float dac[4][8][4];
    #pragma unroll
    for (int mf = 0; mf < 4; ++mf)
        #pragma unroll
        for (int nf = 0; nf < 8; ++nf)
            dac[mf][nf][0] = dac[mf][nf][1] = dac[mf][nf][2] = dac[mf][nf][3] = 0.f;
    float ds[4] = {0.f, 0.f, 0.f, 0.f};

    const float* A0 = sVi + (wi * 32 + g) * DD;          // GEMM1 A base
    const float* B1 = sVj + (wj * 32 + g) * VJS + tg;    // GEMM1 B base
    const float* E0 = sE  + (rb * 64 + g) * TJ;          // GEMM2 A base
    const float* B2 = sVj + tg * VJS + cb * 64 + g;      // GEMM2 B base

    for (int t = 0; t < NITER; ++t) {
        // ---- GEMM1: S(32x32) = Vi . Vj^T over K=256 ----
        float cac[2][4][4];
        #pragma unroll
        for (int mf = 0; mf < 2; ++mf)
            #pragma unroll
            for (int nf = 0; nf < 4; ++nf)
                cac[mf][nf][0] = cac[mf][nf][1] = cac[mf][nf][2] = cac[mf][nf][3] = 0.f;

        #pragma unroll 8
        for (int k0 = 0; k0 < DD; k0 += 8) {
            unsigned ka = ((unsigned)(k0 + tg)) ^ xg;
            unsigned kb = ((unsigned)(k0 + 4 + tg)) ^ xg;
            unsigned a[2][4];
            #pragma unroll
            for (int mf = 0; mf < 2; ++mf) {
                const float* Ap = A0 + mf * 16 * DD;
                a[mf][0] = __float_as_uint(Ap[ka]);
                a[mf][1] = __float_as_uint(Ap[8 * DD + ka]);
                a[mf][2] = __float_as_uint(Ap[kb]);
                a[mf][3] = __float_as_uint(Ap[8 * DD + kb]);
            }
            #pragma unroll
            for (int nf = 0; nf < 4; ++nf) {
                unsigned b0 = __float_as_uint(B1[nf * 8 * VJS + k0]);
                unsigned b1 = __float_as_uint(B1[nf * 8 * VJS + k0 + 4]);
                mma8(cac[0][nf], a[0][0], a[0][1], a[0][2], a[0][3], b0, b1);
                mma8(cac[1][nf], a[1][0], a[1][1], a[1][2], a[1][3], b0, b1);
            }
        }

        // ---- epilogue: softsign, ds partials, E -> smem (tf32, compensated) ----
        #pragma unroll
        for (int mf = 0; mf < 2; ++mf) {
            #pragma unroll
            for (int nf = 0; nf < 4; ++nf) {
                float2 sv = *(const float2*)(sSt + wj * 32 + nf * 8 + 2 * tg);
                float s00 = cac[mf][nf][0] * SCALE1, s01 = cac[mf][nf][1] * SCALE1;
                float s10 = cac[mf][nf][2] * SCALE1, s11 = cac[mf][nf][3] * SCALE1;
                float e00 = __fdividef(s00, 1.0f + fabsf(s00));
                float e01 = __fdividef(s01, 1.0f + fabsf(s01));
                float e10 = __fdividef(s10, 1.0f + fabsf(s10));
                float e11 = __fdividef(s11, 1.0f + fabsf(s11));
                ds[2 * mf]     = fmaf(e00, sv.x, fmaf(e01, sv.y, ds[2 * mf]));
                ds[2 * mf + 1] = fmaf(e10, sv.x, fmaf(e11, sv.y, ds[2 * mf + 1]));
                unsigned jc = ((unsigned)(wj * 32 + nf * 8 + 2 * tg)) ^ xg;
                int r0 = wi * 32 + mf * 16 + g;
                *(float2*)(sE + r0 * TJ + jc) =
                    make_float2(rnaf(e00 * ECOMP), rnaf(e01 * ECOMP));
                *(float2*)(sE + (r0 + 8) * TJ + jc) =
                    make_float2(rnaf(e10 * ECOMP), rnaf(e11 * ECOMP));
            }
        }
        __syncthreads();   // A: E complete

        // ---- GEMM2: D(64x64) += E . Vj over K=64 ----
        #pragma unroll
        for (int kk = 0; kk < 8; ++kk) {
            unsigned ka = ((unsigned)(kk * 8 + tg)) ^ xg;
            unsigned kb = ((unsigned)(kk * 8 + 4 + tg)) ^ xg;
            unsigned a[4][4];
            #pragma unroll
            for (int mf = 0; mf < 4; ++mf) {
                const float* Ep = E0 + mf * 16 * TJ;
                a[mf][0] = __float_as_uint(Ep[ka]);
                a[mf][1] = __float_as_uint(Ep[8 * TJ + ka]);
                a[mf][2] = __float_as_uint(Ep[kb]);
                a[mf][3] = __float_as_uint(Ep[8 * TJ + kb]);
            }
            const float* Bk = B2 + kk * 8 * VJS;
            #pragma unroll
            for (int nf = 0; nf < 8; ++nf) {
                unsigned b0 = __float_as_uint(Bk[nf * 8]);
                unsigned b1 = __float_as_uint(Bk[4 * VJS + nf * 8]);
                #pragma unroll
                for (int mf = 0; mf < 4; ++mf)
                    mma8(dac[mf][nf], a[mf][0], a[mf][1], a[mf][2], a[mf][3], b0, b1);
            }
        }
        __syncthreads();   // B: sVj / sE / sSt free

        // ---- cp.async fill Vj(t+1) + state(t+1) ----
        if (t + 1 < NITER) {
            const float* gsrc = valb + (size_t)(t + 1) * TJ * DD;
            #pragma unroll
            for (int it = 0; it < 16; ++it) {
                int idx = tid + it * NT;
                int r = idx >> 6, c = idx & 63;
                CP16(sbVj + (unsigned)(r * VJS + c * 4) * 4, gsrc + r * DD + c * 4);
            }
            if (tid < TJ) CP4(sbSt + tid * 4, stb + (t + 1) * TJ + tid);
            CP_COMMIT(); CP_WAIT0();
            __syncthreads();   // C: new tile visible
        }
    }

    // ---- delta_state: quad reduce, cross-warp (wj) reduce via smem ----
    #pragma unroll
    for (int q = 0; q < 4; ++q) {
        ds[q] += __shfl_xor_sync(0xFFFFFFFFu, ds[q], 1);
        ds[q] += __shfl_xor_sync(0xFFFFFFFFu, ds[q], 2);
    }
    if (tg == 0) {
        #pragma unroll
        for (int q = 0; q < 4; ++q) {
            int row = wi * 32 + (q >> 1) * 16 + (q & 1) * 8 + g;
            sRed[wj * TM + row] = ds[q];
        }
    }
    __syncthreads();
    if (tid < TM)
        out[(size_t)b * NN + i0 + tid] = sRed[tid] + sRed[TM + tid];

    // ---- delta_val store ----
    float* ov = out + (size_t)BB * NN
              + ((size_t)b * NN + i0 + rb * 64) * DD + cb * 64;
    #pragma unroll
    for (int mf = 0; mf < 4; ++mf) {
        #pragma unroll
        for (int nf = 0; nf < 8; ++nf) {
            int col = nf * 8 + 2 * tg;
            size_t r0 = (size_t)(mf * 16 + g) * DD;
            *(float2*)(ov + r0 + col)            = make_float2(dac[mf][nf][0], dac[mf][nf][1]);
            *(float2*)(ov + r0 + 8 * DD + col)   = make_float2(dac[mf][nf][2], dac[mf][nf][3]);
        }
    }
}

extern "C" void kernel_launch(void* const* d_in, const int* in_sizes, int n_in,
                              void* d_out, int out_size)
{
    const float* val   = (const float*)d_in[0];
    const float* state = (const float*)d_in[1];
    float* out = (float*)d_out;

    cudaFuncSetAttribute(prop_mma2, cudaFuncAttributeMaxDynamicSharedMemorySize, SMEM_BYTES);

    dim3 grid(NN / TM, BB);
    prop_mma2<<<grid, NT, SMEM_BYTES>>>(val, state, out);
}

// round 17
// speedup vs baseline: 7.5438x; 1.3379x over previous
#include <cuda_runtime.h>
#include <cuda_fp16.h>
#include <cstdint>

#define BB 4
#define NN 4096
#define DD 256
#define TM 128
#define TJ 64
#define NITER (NN / TJ)   // 64
#define NT 256            // 8 warps

// smem byte map
#define OFF_VI  0u        // half[128][256] swizzled, 65536 B
#define OFF_VJ  65536u    // 2 x half[64][256], 32768 B each
#define VJB     32768u
#define OFF_E   131072u   // half[128][64] swizzled, 16384 B
#define OFF_ST  147456u   // 2 x float[64]
#define OFF_RED 147968u   // 2 x float[128]
#define SMEM_BYTES 148992

static __device__ __forceinline__ unsigned smem_u32(const void* p) {
    unsigned a;
    asm("{ .reg .u64 t; cvta.to.shared.u64 t, %1; cvt.u32.u64 %0, t; }" : "=r"(a) : "l"(p));
    return a;
}
static __device__ __forceinline__ unsigned packh2(float lo, float hi) {
    unsigned u; asm("cvt.rn.f16x2.f32 %0, %1, %2;" : "=r"(u) : "f"(hi), "f"(lo));
    return u;
}
static __device__ __forceinline__ void mma16(float c[4],
        unsigned a0, unsigned a1, unsigned a2, unsigned a3,
        unsigned b0, unsigned b1) {
    asm volatile(
        "mma.sync.aligned.m16n8k16.row.col.f32.f16.f16.f32 "
        "{%0,%1,%2,%3},{%4,%5,%6,%7},{%8,%9},{%0,%1,%2,%3};"
        : "+f"(c[0]), "+f"(c[1]), "+f"(c[2]), "+f"(c[3])
        : "r"(a0), "r"(a1), "r"(a2), "r"(a3), "r"(b0), "r"(b1));
}
#define LDSM4(R, A) asm volatile( \
    "ldmatrix.sync.aligned.m8n8.x4.shared.b16 {%0,%1,%2,%3}, [%4];" \
    : "=r"((R)[0]), "=r"((R)[1]), "=r"((R)[2]), "=r"((R)[3]) : "r"(A))
#define LDSM4T(R, A) asm volatile( \
    "ldmatrix.sync.aligned.m8n8.x4.trans.shared.b16 {%0,%1,%2,%3}, [%4];" \
    : "=r"((R)[0]), "=r"((R)[1]), "=r"((R)[2]), "=r"((R)[3]) : "r"(A))

__global__ __launch_bounds__(NT)
void prop_h(const float* __restrict__ val,
            const float* __restrict__ state,
            float* __restrict__ out)
{
    extern __shared__ char smem[];
    const unsigned sb = smem_u32(smem);
    float* sStF  = (float*)(smem + OFF_ST);
    float* sRed  = (float*)(smem + OFF_RED);

    const int tid  = threadIdx.x;
    const int wid  = tid >> 5;
    const int lane = tid & 31;
    const int g    = lane >> 2;
    const int tg   = lane & 3;
    const unsigned l7 = lane & 7;
    const unsigned l3 = (lane >> 3) & 1;
    const unsigned l4 = (unsigned)lane >> 4;

    const int wi = wid >> 1, wj = wid & 1;   // GEMM1: 4(i) x 2(j), 32x32 tiles
    const int rb = wid >> 2, cb = wid & 3;   // GEMM2: 2(i) x 4(d), 64x64 tiles

    const int b  = blockIdx.y;
    const int i0 = blockIdx.x * TM;
    const float* valb = val + (size_t)b * NN * DD;
    const float* stb  = state + (size_t)b * NN;

    // ---- fill Vi (fp16, swizzled) ----
    {
        const float4* gv = (const float4*)(valb + (size_t)i0 * DD);
        #pragma unroll
        for (int it = 0; it < 16; ++it) {
            int idx = tid + it * NT;          // 0..4095 chunks
            int r = idx >> 5, ch = idx & 31;
            float4 v0 = gv[r * 64 + ch * 2], v1 = gv[r * 64 + ch * 2 + 1];
            *(uint4*)(smem + OFF_VI + r * 512 + (((unsigned)ch ^ (r & 7)) << 4)) =
                make_uint4(packh2(v0.x, v0.y), packh2(v0.z, v0.w),
                           packh2(v1.x, v1.y), packh2(v1.z, v1.w));
        }
    }
    // ---- fill Vj buf0 + state0 ----
    {
        const float4* gv = (const float4*)valb;
        #pragma unroll
        for (int it = 0; it < 8; ++it) {
            int idx = tid + it * NT;          // 0..2047 chunks
            int r = idx >> 5, ch = idx & 31;
            float4 v0 = gv[r * 64 + ch * 2], v1 = gv[r * 64 + ch * 2 + 1];
            *(uint4*)(smem + OFF_VJ + r * 512 + (((unsigned)ch ^ (r & 7)) << 4)) =
                make_uint4(packh2(v0.x, v0.y), packh2(v0.z, v0.w),
                           packh2(v1.x, v1.y), packh2(v1.z, v1.w));
        }
        if (tid < TJ) sStF[tid] = stb[tid];
    }
    __syncthreads();

    // ldmatrix row-base precomputes (byte offsets)
    unsigned rA0 = (unsigned)(wi * 32 + 0  + l7 + l3 * 8) * 512;   // G1 A mf=0
    unsigned rA1 = (unsigned)(wi * 32 + 16 + l7 + l3 * 8) * 512;   // G1 A mf=1
    unsigned rB0 = (unsigned)(wj * 32 + 0  + l7 + l4 * 8) * 512;   // G1 B p=0
    unsigned rB1 = (unsigned)(wj * 32 + 16 + l7 + l4 * 8) * 512;   // G1 B p=1
    unsigned rE[4];
    #pragma unroll
    for (int mf = 0; mf < 4; ++mf)
        rE[mf] = (unsigned)(rb * 64 + mf * 16 + l7 + l3 * 8) * 128;

    float dac[4][8][4];
    #pragma unroll
    for (int mf = 0; mf < 4; ++mf)
        #pragma unroll
        for (int nf = 0; nf < 8; ++nf)
            dac[mf][nf][0] = dac[mf][nf][1] = dac[mf][nf][2] = dac[mf][nf][3] = 0.f;
    float ds[4] = {0.f, 0.f, 0.f, 0.f};

    for (int t = 0; t < NITER; ++t) {
        const int buf = t & 1;
        const unsigned vjB = sb + OFF_VJ + (unsigned)buf * VJB;
        const bool pre = (t + 1 < NITER);
        const float4* gn = (const float4*)(valb + (size_t)(t + 1) * TJ * DD);

        // phase-A prefetch (rows 0..31 of next Vj)
        float4 pfa[8];
        if (pre) {
            #pragma unroll
            for (int it = 0; it < 4; ++it) {
                int idx = tid + it * NT;
                int r = idx >> 5, ch = idx & 31;
                pfa[2 * it]     = gn[r * 64 + ch * 2];
                pfa[2 * it + 1] = gn[r * 64 + ch * 2 + 1];
            }
        }

        // ---- GEMM1: S(32x32) = Vi . Vj^T, K=256, fp16 ----
        float cac[2][4][4];
        #pragma unroll
        for (int mf = 0; mf < 2; ++mf)
            #pragma unroll
            for (int nf = 0; nf < 4; ++nf)
                cac[mf][nf][0] = cac[mf][nf][1] = cac[mf][nf][2] = cac[mf][nf][3] = 0.f;

        #pragma unroll
        for (int ks = 0; ks < 16; ++ks) {
            const unsigned kc = (unsigned)ks * 2;
            unsigned a[2][4], bf[2][4];
            LDSM4(a[0], sb + OFF_VI + rA0 + (((kc + l4) ^ l7) << 4));
            LDSM4(a[1], sb + OFF_VI + rA1 + (((kc + l4) ^ l7) << 4));
            LDSM4(bf[0], vjB + rB0 + (((kc + l3) ^ l7) << 4));
            LDSM4(bf[1], vjB + rB1 + (((kc + l3) ^ l7) << 4));
            #pragma unroll
            for (int p = 0; p < 2; ++p)
                #pragma unroll
                for (int h = 0; h < 2; ++h) {
                    const int nf = p * 2 + h;
                    mma16(cac[0][nf], a[0][0], a[0][1], a[0][2], a[0][3],
                          bf[p][2 * h], bf[p][2 * h + 1]);
                    mma16(cac[1][nf], a[1][0], a[1][1], a[1][2], a[1][3],
                          bf[p][2 * h], bf[p][2 * h + 1]);
                }
        }

        // ---- epilogue: softsign, ds, E -> smem (fp16) ----
        #pragma unroll
        for (int mf = 0; mf < 2; ++mf) {
            #pragma unroll
            for (int nf = 0; nf < 4; ++nf) {
                const int col = wj * 32 + nf * 8 + 2 * tg;
                float2 sv = *(const float2*)(sStF + buf * TJ + col);
                float s00 = cac[mf][nf][0] * 0.0625f, s01 = cac[mf][nf][1] * 0.0625f;
                float s10 = cac[mf][nf][2] * 0.0625f, s11 = cac[mf][nf][3] * 0.0625f;
                float e00 = __fdividef(s00, 1.0f + fabsf(s00));
                float e01 = __fdividef(s01, 1.0f + fabsf(s01));
                float e10 = __fdividef(s10, 1.0f + fabsf(s10));
                float e11 = __fdividef(s11, 1.0f + fabsf(s11));
                ds[2 * mf]     = fmaf(e00, sv.x, fmaf(e01, sv.y, ds[2 * mf]));
                ds[2 * mf + 1] = fmaf(e10, sv.x, fmaf(e11, sv.y, ds[2 * mf + 1]));
                const int r0 = wi * 32 + mf * 16 + g;
                const unsigned cswz = ((((unsigned)col >> 3) ^ (unsigned)g) << 4) + (col & 7) * 2;
                *(unsigned*)(smem + OFF_E + r0 * 128 + cswz)       = packh2(e00, e01);
                *(unsigned*)(smem + OFF_E + (r0 + 8) * 128 + cswz) = packh2(e10, e11);
            }
        }
        // commit phase-A prefetch to alt buffer
        if (pre) {
            char* db = smem + OFF_VJ + (buf ^ 1) * VJB;
            #pragma unroll
            for (int it = 0; it < 4; ++it) {
                int idx = tid + it * NT;
                int r = idx >> 5, ch = idx & 31;
                *(uint4*)(db + r * 512 + (((unsigned)ch ^ (r & 7)) << 4)) =
                    make_uint4(packh2(pfa[2*it].x, pfa[2*it].y), packh2(pfa[2*it].z, pfa[2*it].w),
                               packh2(pfa[2*it+1].x, pfa[2*it+1].y), packh2(pfa[2*it+1].z, pfa[2*it+1].w));
            }
        }
        __syncthreads();   // A: E visible to all

        // phase-B prefetch (rows 32..63) + state
        float4 pfb[8];
        float stv = 0.f;
        if (pre) {
            #pragma unroll
            for (int it = 4; it < 8; ++it) {
                int idx = tid + it * NT;
                int r = idx >> 5, ch = idx & 31;
                pfb[2 * (it - 4)]     = gn[r * 64 + ch * 2];
                pfb[2 * (it - 4) + 1] = gn[r * 64 + ch * 2 + 1];
            }
            if (tid < TJ) stv = stb[(t + 1) * TJ + tid];
        }

        // ---- GEMM2: D(64x64) += E . Vj, K=64, fp16 ----
        #pragma unroll
        for (int kk = 0; kk < 4; ++kk) {
            const unsigned kc = (unsigned)kk * 2;
            unsigned ae[4][4];
            #pragma unroll
            for (int mf = 0; mf < 4; ++mf)
                LDSM4(ae[mf], sb + OFF_E + rE[mf] + (((kc + l4) ^ l7) << 4));
            const unsigned rowT = vjB + (unsigned)(kk * 16 + l7 + l3 * 8) * 512;
            #pragma unroll
            for (int p = 0; p < 4; ++p) {
                unsigned bv[4];
                LDSM4T(bv, rowT + ((((unsigned)(cb * 8 + p * 2) + l4) ^ l7) << 4));
                #pragma unroll
                for (int h = 0; h < 2; ++h) {
                    const int nf = p * 2 + h;
                    #pragma unroll
                    for (int mf = 0; mf < 4; ++mf)
                        mma16(dac[mf][nf], ae[mf][0], ae[mf][1], ae[mf][2], ae[mf][3],
                              bv[2 * h], bv[2 * h + 1]);
                }
            }
        }

        // commit phase-B prefetch + state
        if (pre) {
            char* db = smem + OFF_VJ + (buf ^ 1) * VJB;
            #pragma unroll
            for (int it = 4; it < 8; ++it) {
                int idx = tid + it * NT;
                int r = idx >> 5, ch = idx & 31;
                const float4 v0 = pfb[2 * (it - 4)], v1 = pfb[2 * (it - 4) + 1];
                *(uint4*)(db + r * 512 + (((unsigned)ch ^ (r & 7)) << 4)) =
                    make_uint4(packh2(v0.x, v0.y), packh2(v0.z, v0.w),
                               packh2(v1.x, v1.y), packh2(v1.z, v1.w));
            }
            if (tid < TJ) sStF[(buf ^ 1) * TJ + tid] = stv;
        }
        __syncthreads();   // B: next Vj/state ready, E free
    }

    // ---- delta_state: quad reduce + cross-wj reduce ----
    #pragma unroll
    for (int q = 0; q < 4; ++q) {
        ds[q] += __shfl_xor_sync(0xFFFFFFFFu, ds[q], 1);
        ds[q] += __shfl_xor_sync(0xFFFFFFFFu, ds[q], 2);
    }
    if (tg == 0) {
        #pragma unroll
        for (int q = 0; q < 4; ++q) {
            int row = wi * 32 + (q >> 1) * 16 + (q & 1) * 8 + g;
            sRed[wj * TM + row] = ds[q];
        }
    }
    __syncthreads();
    if (tid < TM)
        out[(size_t)b * NN + i0 + tid] = sRed[tid] + sRed[TM + tid];

    // ---- delta_val store ----
    float* ov = out + (size_t)BB * NN
              + ((size_t)b * NN + i0 + rb * 64) * DD + cb * 64;
    #pragma unroll
    for (int mf = 0; mf < 4; ++mf) {
        #pragma unroll
        for (int nf = 0; nf < 8; ++nf) {
            int col = nf * 8 + 2 * tg;
            size_t r0 = (size_t)(mf * 16 + g) * DD;
            *(float2*)(ov + r0 + col)          = make_float2(dac[mf][nf][0], dac[mf][nf][1]);
            *(float2*)(ov + r0 + 8 * DD + col) = make_float2(dac[mf][nf][2], dac[mf][nf][3]);
        }
    }
}

extern "C" void kernel_launch(void* const* d_in, const int* in_sizes, int n_in,
                              void* d_out, int out_size)
{
    const float* val   = (const float*)d_in[0];
    const float* state = (const float*)d_in[1];
    float* out = (float*)d_out;

    cudaFuncSetAttribute(prop_h, cudaFuncAttributeMaxDynamicSharedMemorySize, SMEM_BYTES);

    dim3 grid(NN / TM, BB);
    prop_h<<<grid, NT, SMEM_BYTES>>>(val, state, out);
}